// round 13
// baseline (speedup 1.0000x reference)
#include <cuda_runtime.h>
#include <math.h>

#define NMAX 100000
#define EMAX 640000
#define NH 8
#define NC 16
#define NHC 128
#define NG 64
#define SLOTS 64

typedef unsigned long long u64;

// ---- scratch (static device globals; no allocation) ----
static __device__ float g_feat[NMAX * NHC];
static __device__ float g_hbuf[NMAX * NHC];
static __device__ float g_asrc[NMAX * NH];
static __device__ float g_adst[NMAX * NH];
static __device__ float g_loop[NMAX];               // SUM of incoming eattr (mean taken in k_gat)
static __device__ int   g_deg [NMAX];
static __device__ int2  g_badj[NMAX * SLOTS + 8];   // (src, ea bits) + pad for prefetch
static __device__ float g_shead[3 * NH];
static __device__ float g_gsum[NG * NHC];
static __device__ float g_gcnt[NG];

// ---- packed f32x2 helpers ----
__device__ __forceinline__ u64 ffma2(u64 a, u64 b, u64 c) {
    u64 r; asm("fma.rn.f32x2 %0, %1, %2, %3;" : "=l"(r) : "l"(a), "l"(b), "l"(c)); return r;
}
__device__ __forceinline__ u64 dupf(float x) {
    u64 r; asm("mov.b64 %0, {%1, %1};" : "=l"(r) : "f"(x)); return r;
}
__device__ __forceinline__ float2 unpack2(u64 v) {
    float2 r; asm("mov.b64 {%0, %1}, %2;" : "=f"(r.x), "=f"(r.y) : "l"(v)); return r;
}

// ================= K1: fused prep (transform0 | zero | pool_zero | shead) =================
__global__ void k_prep(const float* __restrict__ x,
                       const float* __restrict__ w,
                       const float* __restrict__ a_s,
                       const float* __restrict__ a_d,
                       const float* __restrict__ we0, const float* __restrict__ ae0,
                       const float* __restrict__ we1, const float* __restrict__ ae1,
                       const float* __restrict__ we2, const float* __restrict__ ae2,
                       int n, int tb0, int zb, int pz) {
    int bid = blockIdx.x;
    if (bid < tb0) {
        int gid = bid * 256 + threadIdx.x;
        int node = gid >> 5;
        if (node >= n) return;
        int c = gid & 31;
        float4 xv = *(const float4*)&x[node * 4];
        float4 w0 = *(const float4*)&w[0 * NHC + c * 4];
        float4 w1 = *(const float4*)&w[1 * NHC + c * 4];
        float4 w2 = *(const float4*)&w[2 * NHC + c * 4];
        float4 w3 = *(const float4*)&w[3 * NHC + c * 4];
        float4 acc;
        acc.x = xv.x * w0.x + xv.y * w1.x + xv.z * w2.x + xv.w * w3.x;
        acc.y = xv.x * w0.y + xv.y * w1.y + xv.z * w2.y + xv.w * w3.y;
        acc.z = xv.x * w0.z + xv.y * w1.z + xv.z * w2.z + xv.w * w3.z;
        acc.w = xv.x * w0.w + xv.y * w1.w + xv.z * w2.w + xv.w * w3.w;
        *(float4*)&g_hbuf[node * NHC + c * 4] = acc;
        float4 asv = *(const float4*)&a_s[c * 4];
        float4 adv = *(const float4*)&a_d[c * 4];
        float vs = acc.x * asv.x + acc.y * asv.y + acc.z * asv.z + acc.w * asv.w;
        float vd = acc.x * adv.x + acc.y * adv.y + acc.z * adv.z + acc.w * adv.w;
        vs += __shfl_down_sync(0xffffffffu, vs, 2, 4);
        vs += __shfl_down_sync(0xffffffffu, vs, 1, 4);
        vd += __shfl_down_sync(0xffffffffu, vd, 2, 4);
        vd += __shfl_down_sync(0xffffffffu, vd, 1, 4);
        if ((c & 3) == 0) {
            g_asrc[node * NH + (c >> 2)] = vs;
            g_adst[node * NH + (c >> 2)] = vd;
        }
    } else if (bid < tb0 + zb) {
        int i = (bid - tb0) * 256 + threadIdx.x;
        if (i < n) { g_deg[i] = 0; g_loop[i] = 0.0f; }
    } else if (bid < tb0 + zb + pz) {
        int i = (bid - tb0 - zb) * 256 + threadIdx.x;
        if (i < NG * NHC) g_gsum[i] = 0.0f;
        if (i < NG) g_gcnt[i] = 0.0f;
    } else {
        int t = threadIdx.x;
        if (t >= 24) return;
        int l = t >> 3, h = t & 7;
        const float* we = (l == 0) ? we0 : (l == 1) ? we1 : we2;
        const float* ae = (l == 0) ? ae0 : (l == 1) ? ae1 : ae2;
        float s = 0.0f;
        for (int cc = 0; cc < NC; cc++) s += we[h * NC + cc] * ae[h * NC + cc];
        g_shead[t] = s;
    }
}

// ================= K2: bucket scatter =================
__global__ void k_scatter(const int* __restrict__ src, const int* __restrict__ dst,
                          const float* __restrict__ eattr, int E) {
    int e = blockIdx.x * blockDim.x + threadIdx.x;
    if (e < E) {
        int d = dst[e];
        float ea = eattr[e];
        int slot = atomicAdd(&g_deg[d], 1);
        if (slot < SLOTS) g_badj[d * SLOTS + slot] = make_int2(src[e], __float_as_int(ea));
        atomicAdd(&g_loop[d], ea);
    }
}

// ---- layers 1/2 transform: K=128 GEMM, FFMA2, 64 nodes/block ----
__global__ void __launch_bounds__(512, 2) k_transform128(
        const float* __restrict__ w,
        const float* __restrict__ a_s,
        const float* __restrict__ a_d, int n) {
    __shared__ float xs[64 * NHC];           // 32KB x-tile
    int tile = blockIdx.x * 64;
    int t = threadIdx.x;
    for (int i = t; i < 64 * NHC / 4; i += 512) {
        int nl = i >> 5;
        int node = tile + nl;
        float4 v = make_float4(0.f, 0.f, 0.f, 0.f);
        if (node < n) v = *(const float4*)&g_feat[node * NHC + (i & 31) * 4];
        *(float4*)&xs[nl * NHC + (i & 31) * 4] = v;
    }
    __syncthreads();

    int c = t & 31;
    int m = t >> 5;
    const float* xr0 = &xs[(m * 4 + 0) * NHC];
    const float* xr1 = &xs[(m * 4 + 1) * NHC];
    const float* xr2 = &xs[(m * 4 + 2) * NHC];
    const float* xr3 = &xs[(m * 4 + 3) * NHC];
    u64 acc[4][2] = {{0,0},{0,0},{0,0},{0,0}};
    const ulonglong2* wp = (const ulonglong2*)&w[c * 4];
#pragma unroll 4
    for (int k = 0; k < NHC; k++) {
        ulonglong2 wv = wp[k * (NHC / 4)];
        u64 d0 = dupf(xr0[k]);
        u64 d1 = dupf(xr1[k]);
        u64 d2 = dupf(xr2[k]);
        u64 d3 = dupf(xr3[k]);
        acc[0][0] = ffma2(d0, wv.x, acc[0][0]); acc[0][1] = ffma2(d0, wv.y, acc[0][1]);
        acc[1][0] = ffma2(d1, wv.x, acc[1][0]); acc[1][1] = ffma2(d1, wv.y, acc[1][1]);
        acc[2][0] = ffma2(d2, wv.x, acc[2][0]); acc[2][1] = ffma2(d2, wv.y, acc[2][1]);
        acc[3][0] = ffma2(d3, wv.x, acc[3][0]); acc[3][1] = ffma2(d3, wv.y, acc[3][1]);
    }
    float4 a4[4];
#pragma unroll
    for (int i = 0; i < 4; i++) {
        float2 lo = unpack2(acc[i][0]);
        float2 hi = unpack2(acc[i][1]);
        a4[i] = make_float4(lo.x, lo.y, hi.x, hi.y);
    }
    float4 asv = *(const float4*)&a_s[c * 4];
    float4 adv = *(const float4*)&a_d[c * 4];
    float vs[4], vd[4];
#pragma unroll
    for (int i = 0; i < 4; i++) {
        vs[i] = a4[i].x*asv.x + a4[i].y*asv.y + a4[i].z*asv.z + a4[i].w*asv.w;
        vd[i] = a4[i].x*adv.x + a4[i].y*adv.y + a4[i].z*adv.z + a4[i].w*adv.w;
    }
#pragma unroll
    for (int off = 2; off > 0; off >>= 1) {
#pragma unroll
        for (int i = 0; i < 4; i++) {
            vs[i] += __shfl_down_sync(0xffffffffu, vs[i], off, 4);
            vd[i] += __shfl_down_sync(0xffffffffu, vd[i], off, 4);
        }
    }
    int node0 = tile + m * 4;
    int h = c >> 2;
    if ((c & 3) == 0) {
#pragma unroll
        for (int i = 0; i < 4; i++)
            if (node0 + i < n) {
                g_asrc[(node0+i)*NH+h] = vs[i];
                g_adst[(node0+i)*NH+h] = vd[i];
            }
    }
#pragma unroll
    for (int i = 0; i < 4; i++)
        if (node0 + i < n) *(float4*)&g_hbuf[(node0+i)*NHC + c*4] = a4[i];
}

// ---- fused GAT dst pass: 8-edge int4 prefetch, shfl-free, warp per node ----
// self-loop mean computed inline: loopv = loop_sum / max(deg_full, 1)
__global__ void __launch_bounds__(256) k_gat(const float* __restrict__ b,
                                             int layer, int withLoop, int n) {
    int warp = (blockIdx.x * blockDim.x + threadIdx.x) >> 5;
    int lane = threadIdx.x & 31;
    if (warp >= n) return;
    const int d = warp;
    const int hC = lane >> 2;

    float adst_h  = g_adst[d * NH + hC];
    float shead_h = g_shead[layer * NH + hC];

    int degFull = g_deg[d];
    float loopv = withLoop ? (g_loop[d] / fmaxf((float)degFull, 1.0f)) : 0.0f;

    int deg = min(degFull, SLOTS);
    int degTot = deg + withLoop;
    const int2* ba = &g_badj[d * SLOTS];

    float4 acc = make_float4(0.f, 0.f, 0.f, 0.f);
    float den = 0.0f;

    for (int base = 0; base < degTot; base += 8) {
        int4 q0 = *(const int4*)(ba + base + 0);
        int4 q1 = *(const int4*)(ba + base + 2);
        int4 q2 = *(const int4*)(ba + base + 4);
        int4 q3 = *(const int4*)(ba + base + 6);
        int   sv[8] = {q0.x, q0.z, q1.x, q1.z, q2.x, q2.z, q3.x, q3.z};
        int   ev[8] = {q0.y, q0.w, q1.y, q1.w, q2.y, q2.w, q3.y, q3.w};
#pragma unroll
        for (int j = 0; j < 8; j++) {
            int i = base + j;
            if (i >= degTot) break;
            int s; float ea;
            if (i < deg) { s = sv[j]; ea = __int_as_float(ev[j]); }
            else         { s = d;     ea = loopv; }
            float a = g_asrc[s * NH + hC] + adst_h + ea * shead_h;
            a = a > 0.0f ? a : 0.2f * a;
            float w = __expf(a);
            den += w;
            float4 hv = *(const float4*)&g_hbuf[s * NHC + lane * 4];
            acc.x += w * hv.x; acc.y += w * hv.y; acc.z += w * hv.z; acc.w += w * hv.w;
        }
    }

    float inv = 1.0f / (den + 1e-16f);
    float4 bv = *(const float4*)&b[lane * 4];
    float4 o;
    o.x = fmaxf(acc.x * inv + bv.x, 0.0f);
    o.y = fmaxf(acc.y * inv + bv.y, 0.0f);
    o.z = fmaxf(acc.z * inv + bv.z, 0.0f);
    o.w = fmaxf(acc.w * inv + bv.w, 0.0f);
    *(float4*)&g_feat[d * NHC + lane * 4] = o;
}

// ---- pooling (4-deep software pipeline) ----
__global__ void k_pool(const int* __restrict__ batch, int n) {
    const int CHUNK = 128;
    int n0 = blockIdx.x * CHUNK;
    int j = threadIdx.x;
    int lim = min(CHUNK, n - n0);
    float acc = 0.0f;
    int cur = -1, cl = 0;
    for (int i0 = 0; i0 < lim; i0 += 4) {
        float f[4]; int bi[4];
        int cnt = min(4, lim - i0);
#pragma unroll
        for (int k = 0; k < 4; k++) {
            if (k < cnt) {
                f[k]  = g_feat[(u64)(n0 + i0 + k) * NHC + j];
                bi[k] = batch[n0 + i0 + k];
            }
        }
#pragma unroll
        for (int k = 0; k < 4; k++) {
            if (k >= cnt) break;
            if (bi[k] != cur) {
                if (cur >= 0) {
                    atomicAdd(&g_gsum[cur * NHC + j], acc);
                    if (j == 0) atomicAdd(&g_gcnt[cur], (float)cl);
                }
                cur = bi[k]; acc = 0.0f; cl = 0;
            }
            acc += f[k];
            cl++;
        }
    }
    if (cur >= 0) {
        atomicAdd(&g_gsum[cur * NHC + j], acc);
        if (j == 0) atomicAdd(&g_gcnt[cur], (float)cl);
    }
}

// ---- final MLP head ----
__global__ void k_mlp(const float* __restrict__ fw1, const float* __restrict__ fb1,
                      const float* __restrict__ fw2, const float* __restrict__ fb2,
                      float* __restrict__ out) {
    int g = blockIdx.x, t = threadIdx.x;
    __shared__ float emb[NHC];
    __shared__ float ghs[64];
    float cnt = fmaxf(g_gcnt[g], 1.0f);
    emb[t]      = g_gsum[g * NHC + t] / cnt;
    emb[t + 64] = g_gsum[g * NHC + 64 + t] / cnt;
    __syncthreads();
    float acc = fb1[t];
#pragma unroll 8
    for (int k = 0; k < NHC; k++) acc += emb[k] * fw1[k * 64 + t];
    ghs[t] = fmaxf(acc, 0.0f);
    __syncthreads();
    if (t < 2) {
        float o = fb2[t];
        for (int k = 0; k < 64; k++) o += ghs[k] * fw2[k * 2 + t];
        out[g * 2 + t] = o;
    }
}

extern "C" void kernel_launch(void* const* d_in, const int* in_sizes, int n_in,
                              void* d_out, int out_size) {
    const float* x     = (const float*)d_in[0];
    const int*   ei    = (const int*)d_in[1];
    const float* eattr = (const float*)d_in[2];
    const int*   batch = (const int*)d_in[3];

    const float* W[3]  = {(const float*)d_in[4],  (const float*)d_in[10], (const float*)d_in[16]};
    const float* AS[3] = {(const float*)d_in[5],  (const float*)d_in[11], (const float*)d_in[17]};
    const float* AD[3] = {(const float*)d_in[6],  (const float*)d_in[12], (const float*)d_in[18]};
    const float* WE[3] = {(const float*)d_in[7],  (const float*)d_in[13], (const float*)d_in[19]};
    const float* AE[3] = {(const float*)d_in[8],  (const float*)d_in[14], (const float*)d_in[20]};
    const float* B[3]  = {(const float*)d_in[9],  (const float*)d_in[15], (const float*)d_in[21]};
    const float* fw1 = (const float*)d_in[22];
    const float* fb1 = (const float*)d_in[23];
    const float* fw2 = (const float*)d_in[24];
    const float* fb2 = (const float*)d_in[25];

    int N = in_sizes[3];
    int E = in_sizes[1] / 2;
    const int* src = ei;
    const int* dst = ei + E;

    int tb0 = (N * 32 + 255) / 256;
    int zb  = (N + 255) / 256;
    int pz  = (NG * NHC + 255) / 256;

    // 1: transform0 + zero + pool_zero + shead
    k_prep<<<tb0 + zb + pz + 1, 256>>>(x, W[0], AS[0], AD[0],
                                       WE[0], AE[0], WE[1], AE[1], WE[2], AE[2],
                                       N, tb0, zb, pz);
    // 2: bucket adjacency build (+ loop sums)
    k_scatter<<<(E + 255) / 256, 256>>>(src, dst, eattr, E);

    int gatBlocks  = (N * 32 + 255) / 256;
    int gemmBlocks = (N + 63) / 64;
    // 3: gat layer 0
    k_gat<<<gatBlocks, 256>>>(B[0], 0, 0, N);
    // 4: transform layer 1 (ncu capture slot)
    k_transform128<<<gemmBlocks, 512>>>(W[1], AS[1], AD[1], N);
    k_gat<<<gatBlocks, 256>>>(B[1], 1, 1, N);
    k_transform128<<<gemmBlocks, 512>>>(W[2], AS[2], AD[2], N);
    k_gat<<<gatBlocks, 256>>>(B[2], 2, 1, N);

    k_pool<<<(N + 127) / 128, NHC>>>(batch, N);
    k_mlp<<<NG, 64>>>(fw1, fb1, fw2, fb2, (float*)d_out);
}

// round 14
// speedup vs baseline: 1.0062x; 1.0062x over previous
#include <cuda_runtime.h>
#include <math.h>

#define NMAX 100000
#define EMAX 640000
#define NH 8
#define NC 16
#define NHC 128
#define NG 64
#define SLOTS 64

typedef unsigned long long u64;

// ---- scratch (static device globals; no allocation) ----
static __device__ float g_feat[NMAX * NHC];
static __device__ float g_hbuf[NMAX * NHC];
static __device__ float g_asrc[NMAX * NH];
static __device__ float g_adst[NMAX * NH];
static __device__ float g_loop[NMAX];               // SUM of incoming eattr (mean taken in k_gat)
static __device__ int   g_deg [NMAX];
static __device__ int2  g_badj[NMAX * SLOTS + 8];   // (src, ea bits) + pad for prefetch
static __device__ float g_shead[3 * NH];
static __device__ float g_gsum[NG * NHC];
static __device__ float g_gcnt[NG];

// ---- packed f32x2 helpers ----
__device__ __forceinline__ u64 ffma2(u64 a, u64 b, u64 c) {
    u64 r; asm("fma.rn.f32x2 %0, %1, %2, %3;" : "=l"(r) : "l"(a), "l"(b), "l"(c)); return r;
}
__device__ __forceinline__ u64 dupf(float x) {
    u64 r; asm("mov.b64 %0, {%1, %1};" : "=l"(r) : "f"(x)); return r;
}
__device__ __forceinline__ float2 unpack2(u64 v) {
    float2 r; asm("mov.b64 {%0, %1}, %2;" : "=f"(r.x), "=f"(r.y) : "l"(v)); return r;
}

// ================= K1: fused prep (transform0 | zero | pool_zero | shead) =================
__global__ void k_prep(const float* __restrict__ x,
                       const float* __restrict__ w,
                       const float* __restrict__ a_s,
                       const float* __restrict__ a_d,
                       const float* __restrict__ we0, const float* __restrict__ ae0,
                       const float* __restrict__ we1, const float* __restrict__ ae1,
                       const float* __restrict__ we2, const float* __restrict__ ae2,
                       int n, int tb0, int zb, int pz) {
    int bid = blockIdx.x;
    if (bid < tb0) {
        int gid = bid * 256 + threadIdx.x;
        int node = gid >> 5;
        if (node >= n) return;
        int c = gid & 31;
        float4 xv = *(const float4*)&x[node * 4];
        float4 w0 = *(const float4*)&w[0 * NHC + c * 4];
        float4 w1 = *(const float4*)&w[1 * NHC + c * 4];
        float4 w2 = *(const float4*)&w[2 * NHC + c * 4];
        float4 w3 = *(const float4*)&w[3 * NHC + c * 4];
        float4 acc;
        acc.x = xv.x * w0.x + xv.y * w1.x + xv.z * w2.x + xv.w * w3.x;
        acc.y = xv.x * w0.y + xv.y * w1.y + xv.z * w2.y + xv.w * w3.y;
        acc.z = xv.x * w0.z + xv.y * w1.z + xv.z * w2.z + xv.w * w3.z;
        acc.w = xv.x * w0.w + xv.y * w1.w + xv.z * w2.w + xv.w * w3.w;
        *(float4*)&g_hbuf[node * NHC + c * 4] = acc;
        float4 asv = *(const float4*)&a_s[c * 4];
        float4 adv = *(const float4*)&a_d[c * 4];
        float vs = acc.x * asv.x + acc.y * asv.y + acc.z * asv.z + acc.w * asv.w;
        float vd = acc.x * adv.x + acc.y * adv.y + acc.z * adv.z + acc.w * adv.w;
        vs += __shfl_down_sync(0xffffffffu, vs, 2, 4);
        vs += __shfl_down_sync(0xffffffffu, vs, 1, 4);
        vd += __shfl_down_sync(0xffffffffu, vd, 2, 4);
        vd += __shfl_down_sync(0xffffffffu, vd, 1, 4);
        if ((c & 3) == 0) {
            g_asrc[node * NH + (c >> 2)] = vs;
            g_adst[node * NH + (c >> 2)] = vd;
        }
    } else if (bid < tb0 + zb) {
        int i = (bid - tb0) * 256 + threadIdx.x;
        if (i < n) { g_deg[i] = 0; g_loop[i] = 0.0f; }
    } else if (bid < tb0 + zb + pz) {
        int i = (bid - tb0 - zb) * 256 + threadIdx.x;
        if (i < NG * NHC) g_gsum[i] = 0.0f;
        if (i < NG) g_gcnt[i] = 0.0f;
    } else {
        int t = threadIdx.x;
        if (t >= 24) return;
        int l = t >> 3, h = t & 7;
        const float* we = (l == 0) ? we0 : (l == 1) ? we1 : we2;
        const float* ae = (l == 0) ? ae0 : (l == 1) ? ae1 : ae2;
        float s = 0.0f;
        for (int cc = 0; cc < NC; cc++) s += we[h * NC + cc] * ae[h * NC + cc];
        g_shead[t] = s;
    }
}

// ================= K2: bucket scatter =================
__global__ void k_scatter(const int* __restrict__ src, const int* __restrict__ dst,
                          const float* __restrict__ eattr, int E) {
    int e = blockIdx.x * blockDim.x + threadIdx.x;
    if (e < E) {
        int d = dst[e];
        float ea = eattr[e];
        int slot = atomicAdd(&g_deg[d], 1);
        if (slot < SLOTS) g_badj[d * SLOTS + slot] = make_int2(src[e], __float_as_int(ea));
        atomicAdd(&g_loop[d], ea);
    }
}

// ---- layers 1/2 transform: K=128 GEMM, FFMA2, 64 nodes/block, LDS.128 x-loads ----
__global__ void __launch_bounds__(512, 2) k_transform128(
        const float* __restrict__ w,
        const float* __restrict__ a_s,
        const float* __restrict__ a_d, int n) {
    __shared__ float xs[64 * NHC];           // 32KB x-tile
    int tile = blockIdx.x * 64;
    int t = threadIdx.x;
    for (int i = t; i < 64 * NHC / 4; i += 512) {
        int nl = i >> 5;
        int node = tile + nl;
        float4 v = make_float4(0.f, 0.f, 0.f, 0.f);
        if (node < n) v = *(const float4*)&g_feat[node * NHC + (i & 31) * 4];
        *(float4*)&xs[nl * NHC + (i & 31) * 4] = v;
    }
    __syncthreads();

    int c = t & 31;
    int m = t >> 5;
    const float* xr0 = &xs[(m * 4 + 0) * NHC];
    const float* xr1 = &xs[(m * 4 + 1) * NHC];
    const float* xr2 = &xs[(m * 4 + 2) * NHC];
    const float* xr3 = &xs[(m * 4 + 3) * NHC];
    u64 acc[4][2] = {{0,0},{0,0},{0,0},{0,0}};
    const ulonglong2* wp = (const ulonglong2*)&w[c * 4];
#pragma unroll 2
    for (int k = 0; k < NHC; k += 4) {
        // one LDS.128 per node-row per 4 k-steps (was 4 scalar LDS per k-step)
        float4 x0 = *(const float4*)&xr0[k];
        float4 x1 = *(const float4*)&xr1[k];
        float4 x2 = *(const float4*)&xr2[k];
        float4 x3 = *(const float4*)&xr3[k];
        const float* p0 = &x0.x;
        const float* p1 = &x1.x;
        const float* p2 = &x2.x;
        const float* p3 = &x3.x;
#pragma unroll
        for (int kk = 0; kk < 4; kk++) {
            ulonglong2 wv = wp[(k + kk) * (NHC / 4)];
            u64 d0 = dupf(p0[kk]);
            u64 d1 = dupf(p1[kk]);
            u64 d2 = dupf(p2[kk]);
            u64 d3 = dupf(p3[kk]);
            acc[0][0] = ffma2(d0, wv.x, acc[0][0]); acc[0][1] = ffma2(d0, wv.y, acc[0][1]);
            acc[1][0] = ffma2(d1, wv.x, acc[1][0]); acc[1][1] = ffma2(d1, wv.y, acc[1][1]);
            acc[2][0] = ffma2(d2, wv.x, acc[2][0]); acc[2][1] = ffma2(d2, wv.y, acc[2][1]);
            acc[3][0] = ffma2(d3, wv.x, acc[3][0]); acc[3][1] = ffma2(d3, wv.y, acc[3][1]);
        }
    }
    float4 a4[4];
#pragma unroll
    for (int i = 0; i < 4; i++) {
        float2 lo = unpack2(acc[i][0]);
        float2 hi = unpack2(acc[i][1]);
        a4[i] = make_float4(lo.x, lo.y, hi.x, hi.y);
    }
    float4 asv = *(const float4*)&a_s[c * 4];
    float4 adv = *(const float4*)&a_d[c * 4];
    float vs[4], vd[4];
#pragma unroll
    for (int i = 0; i < 4; i++) {
        vs[i] = a4[i].x*asv.x + a4[i].y*asv.y + a4[i].z*asv.z + a4[i].w*asv.w;
        vd[i] = a4[i].x*adv.x + a4[i].y*adv.y + a4[i].z*adv.z + a4[i].w*adv.w;
    }
#pragma unroll
    for (int off = 2; off > 0; off >>= 1) {
#pragma unroll
        for (int i = 0; i < 4; i++) {
            vs[i] += __shfl_down_sync(0xffffffffu, vs[i], off, 4);
            vd[i] += __shfl_down_sync(0xffffffffu, vd[i], off, 4);
        }
    }
    int node0 = tile + m * 4;
    int h = c >> 2;
    if ((c & 3) == 0) {
#pragma unroll
        for (int i = 0; i < 4; i++)
            if (node0 + i < n) {
                g_asrc[(node0+i)*NH+h] = vs[i];
                g_adst[(node0+i)*NH+h] = vd[i];
            }
    }
#pragma unroll
    for (int i = 0; i < 4; i++)
        if (node0 + i < n) *(float4*)&g_hbuf[(node0+i)*NHC + c*4] = a4[i];
}

// ---- fused GAT dst pass: 8-edge int4 prefetch, shfl-free, warp per node ----
__global__ void __launch_bounds__(256) k_gat(const float* __restrict__ b,
                                             int layer, int withLoop, int n) {
    int warp = (blockIdx.x * blockDim.x + threadIdx.x) >> 5;
    int lane = threadIdx.x & 31;
    if (warp >= n) return;
    const int d = warp;
    const int hC = lane >> 2;

    float adst_h  = g_adst[d * NH + hC];
    float shead_h = g_shead[layer * NH + hC];

    int degFull = g_deg[d];
    float loopv = withLoop ? (g_loop[d] / fmaxf((float)degFull, 1.0f)) : 0.0f;

    int deg = min(degFull, SLOTS);
    int degTot = deg + withLoop;
    const int2* ba = &g_badj[d * SLOTS];

    float4 acc = make_float4(0.f, 0.f, 0.f, 0.f);
    float den = 0.0f;

    for (int base = 0; base < degTot; base += 8) {
        int4 q0 = *(const int4*)(ba + base + 0);
        int4 q1 = *(const int4*)(ba + base + 2);
        int4 q2 = *(const int4*)(ba + base + 4);
        int4 q3 = *(const int4*)(ba + base + 6);
        int   sv[8] = {q0.x, q0.z, q1.x, q1.z, q2.x, q2.z, q3.x, q3.z};
        int   ev[8] = {q0.y, q0.w, q1.y, q1.w, q2.y, q2.w, q3.y, q3.w};
#pragma unroll
        for (int j = 0; j < 8; j++) {
            int i = base + j;
            if (i >= degTot) break;
            int s; float ea;
            if (i < deg) { s = sv[j]; ea = __int_as_float(ev[j]); }
            else         { s = d;     ea = loopv; }
            float a = g_asrc[s * NH + hC] + adst_h + ea * shead_h;
            a = a > 0.0f ? a : 0.2f * a;
            float w = __expf(a);
            den += w;
            float4 hv = *(const float4*)&g_hbuf[s * NHC + lane * 4];
            acc.x += w * hv.x; acc.y += w * hv.y; acc.z += w * hv.z; acc.w += w * hv.w;
        }
    }

    float inv = 1.0f / (den + 1e-16f);
    float4 bv = *(const float4*)&b[lane * 4];
    float4 o;
    o.x = fmaxf(acc.x * inv + bv.x, 0.0f);
    o.y = fmaxf(acc.y * inv + bv.y, 0.0f);
    o.z = fmaxf(acc.z * inv + bv.z, 0.0f);
    o.w = fmaxf(acc.w * inv + bv.w, 0.0f);
    *(float4*)&g_feat[d * NHC + lane * 4] = o;
}

// ---- pooling (4-deep software pipeline) ----
__global__ void k_pool(const int* __restrict__ batch, int n) {
    const int CHUNK = 128;
    int n0 = blockIdx.x * CHUNK;
    int j = threadIdx.x;
    int lim = min(CHUNK, n - n0);
    float acc = 0.0f;
    int cur = -1, cl = 0;
    for (int i0 = 0; i0 < lim; i0 += 4) {
        float f[4]; int bi[4];
        int cnt = min(4, lim - i0);
#pragma unroll
        for (int k = 0; k < 4; k++) {
            if (k < cnt) {
                f[k]  = g_feat[(u64)(n0 + i0 + k) * NHC + j];
                bi[k] = batch[n0 + i0 + k];
            }
        }
#pragma unroll
        for (int k = 0; k < 4; k++) {
            if (k >= cnt) break;
            if (bi[k] != cur) {
                if (cur >= 0) {
                    atomicAdd(&g_gsum[cur * NHC + j], acc);
                    if (j == 0) atomicAdd(&g_gcnt[cur], (float)cl);
                }
                cur = bi[k]; acc = 0.0f; cl = 0;
            }
            acc += f[k];
            cl++;
        }
    }
    if (cur >= 0) {
        atomicAdd(&g_gsum[cur * NHC + j], acc);
        if (j == 0) atomicAdd(&g_gcnt[cur], (float)cl);
    }
}

// ---- final MLP head ----
__global__ void k_mlp(const float* __restrict__ fw1, const float* __restrict__ fb1,
                      const float* __restrict__ fw2, const float* __restrict__ fb2,
                      float* __restrict__ out) {
    int g = blockIdx.x, t = threadIdx.x;
    __shared__ float emb[NHC];
    __shared__ float ghs[64];
    float cnt = fmaxf(g_gcnt[g], 1.0f);
    emb[t]      = g_gsum[g * NHC + t] / cnt;
    emb[t + 64] = g_gsum[g * NHC + 64 + t] / cnt;
    __syncthreads();
    float acc = fb1[t];
#pragma unroll 8
    for (int k = 0; k < NHC; k++) acc += emb[k] * fw1[k * 64 + t];
    ghs[t] = fmaxf(acc, 0.0f);
    __syncthreads();
    if (t < 2) {
        float o = fb2[t];
        for (int k = 0; k < 64; k++) o += ghs[k] * fw2[k * 2 + t];
        out[g * 2 + t] = o;
    }
}

extern "C" void kernel_launch(void* const* d_in, const int* in_sizes, int n_in,
                              void* d_out, int out_size) {
    const float* x     = (const float*)d_in[0];
    const int*   ei    = (const int*)d_in[1];
    const float* eattr = (const float*)d_in[2];
    const int*   batch = (const int*)d_in[3];

    const float* W[3]  = {(const float*)d_in[4],  (const float*)d_in[10], (const float*)d_in[16]};
    const float* AS[3] = {(const float*)d_in[5],  (const float*)d_in[11], (const float*)d_in[17]};
    const float* AD[3] = {(const float*)d_in[6],  (const float*)d_in[12], (const float*)d_in[18]};
    const float* WE[3] = {(const float*)d_in[7],  (const float*)d_in[13], (const float*)d_in[19]};
    const float* AE[3] = {(const float*)d_in[8],  (const float*)d_in[14], (const float*)d_in[20]};
    const float* B[3]  = {(const float*)d_in[9],  (const float*)d_in[15], (const float*)d_in[21]};
    const float* fw1 = (const float*)d_in[22];
    const float* fb1 = (const float*)d_in[23];
    const float* fw2 = (const float*)d_in[24];
    const float* fb2 = (const float*)d_in[25];

    int N = in_sizes[3];
    int E = in_sizes[1] / 2;
    const int* src = ei;
    const int* dst = ei + E;

    int tb0 = (N * 32 + 255) / 256;
    int zb  = (N + 255) / 256;
    int pz  = (NG * NHC + 255) / 256;

    // 1: transform0 + zero + pool_zero + shead
    k_prep<<<tb0 + zb + pz + 1, 256>>>(x, W[0], AS[0], AD[0],
                                       WE[0], AE[0], WE[1], AE[1], WE[2], AE[2],
                                       N, tb0, zb, pz);
    // 2: bucket adjacency build (+ loop sums)
    k_scatter<<<(E + 255) / 256, 256>>>(src, dst, eattr, E);

    int gatBlocks  = (N * 32 + 255) / 256;
    int gemmBlocks = (N + 63) / 64;
    // 3: gat layer 0
    k_gat<<<gatBlocks, 256>>>(B[0], 0, 0, N);
    // 4: transform layer 1 (ncu capture slot)
    k_transform128<<<gemmBlocks, 512>>>(W[1], AS[1], AD[1], N);
    k_gat<<<gatBlocks, 256>>>(B[1], 1, 1, N);
    k_transform128<<<gemmBlocks, 512>>>(W[2], AS[2], AD[2], N);
    k_gat<<<gatBlocks, 256>>>(B[2], 2, 1, N);

    k_pool<<<(N + 127) / 128, NHC>>>(batch, N);
    k_mlp<<<NG, 64>>>(fw1, fb1, fw2, fb2, (float*)d_out);
}

// round 15
// speedup vs baseline: 1.0355x; 1.0291x over previous
#include <cuda_runtime.h>
#include <math.h>

#define NMAX 100000
#define EMAX 640000
#define NH 8
#define NC 16
#define NHC 128
#define NG 64
#define SLOTS 64

typedef unsigned long long u64;

// ---- scratch (static device globals; no allocation) ----
static __device__ float g_feat[NMAX * NHC];
static __device__ float g_hbuf[NMAX * NHC];
static __device__ float g_asrc[NMAX * NH];
static __device__ float g_adst[NMAX * NH];
static __device__ float g_loop[NMAX];               // SUM of incoming eattr (mean taken in k_gat)
static __device__ int   g_deg [NMAX];
static __device__ int2  g_badj[NMAX * SLOTS + 8];   // (src, ea bits) + pad for prefetch
static __device__ float g_shead[3 * NH];
static __device__ float g_gsum[NG * NHC];
static __device__ float g_gcnt[NG];

// ---- packed f32x2 helpers ----
__device__ __forceinline__ u64 ffma2(u64 a, u64 b, u64 c) {
    u64 r; asm("fma.rn.f32x2 %0, %1, %2, %3;" : "=l"(r) : "l"(a), "l"(b), "l"(c)); return r;
}
__device__ __forceinline__ u64 dupf(float x) {
    u64 r; asm("mov.b64 %0, {%1, %1};" : "=l"(r) : "f"(x)); return r;
}
__device__ __forceinline__ float2 unpack2(u64 v) {
    float2 r; asm("mov.b64 {%0, %1}, %2;" : "=f"(r.x), "=f"(r.y) : "l"(v)); return r;
}

// ================= K1: fused prep (transform0 | zero | pool_zero | shead) =================
__global__ void k_prep(const float* __restrict__ x,
                       const float* __restrict__ w,
                       const float* __restrict__ a_s,
                       const float* __restrict__ a_d,
                       const float* __restrict__ we0, const float* __restrict__ ae0,
                       const float* __restrict__ we1, const float* __restrict__ ae1,
                       const float* __restrict__ we2, const float* __restrict__ ae2,
                       int n, int tb0, int zb, int pz) {
    int bid = blockIdx.x;
    if (bid < tb0) {
        int gid = bid * 256 + threadIdx.x;
        int node = gid >> 5;
        if (node >= n) return;
        int c = gid & 31;
        float4 xv = *(const float4*)&x[node * 4];
        float4 w0 = *(const float4*)&w[0 * NHC + c * 4];
        float4 w1 = *(const float4*)&w[1 * NHC + c * 4];
        float4 w2 = *(const float4*)&w[2 * NHC + c * 4];
        float4 w3 = *(const float4*)&w[3 * NHC + c * 4];
        float4 acc;
        acc.x = xv.x * w0.x + xv.y * w1.x + xv.z * w2.x + xv.w * w3.x;
        acc.y = xv.x * w0.y + xv.y * w1.y + xv.z * w2.y + xv.w * w3.y;
        acc.z = xv.x * w0.z + xv.y * w1.z + xv.z * w2.z + xv.w * w3.z;
        acc.w = xv.x * w0.w + xv.y * w1.w + xv.z * w2.w + xv.w * w3.w;
        *(float4*)&g_hbuf[node * NHC + c * 4] = acc;
        float4 asv = *(const float4*)&a_s[c * 4];
        float4 adv = *(const float4*)&a_d[c * 4];
        float vs = acc.x * asv.x + acc.y * asv.y + acc.z * asv.z + acc.w * asv.w;
        float vd = acc.x * adv.x + acc.y * adv.y + acc.z * adv.z + acc.w * adv.w;
        vs += __shfl_down_sync(0xffffffffu, vs, 2, 4);
        vs += __shfl_down_sync(0xffffffffu, vs, 1, 4);
        vd += __shfl_down_sync(0xffffffffu, vd, 2, 4);
        vd += __shfl_down_sync(0xffffffffu, vd, 1, 4);
        if ((c & 3) == 0) {
            g_asrc[node * NH + (c >> 2)] = vs;
            g_adst[node * NH + (c >> 2)] = vd;
        }
    } else if (bid < tb0 + zb) {
        int i = (bid - tb0) * 256 + threadIdx.x;
        if (i < n) { g_deg[i] = 0; g_loop[i] = 0.0f; }
    } else if (bid < tb0 + zb + pz) {
        int i = (bid - tb0 - zb) * 256 + threadIdx.x;
        if (i < NG * NHC) g_gsum[i] = 0.0f;
        if (i < NG) g_gcnt[i] = 0.0f;
    } else {
        int t = threadIdx.x;
        if (t >= 24) return;
        int l = t >> 3, h = t & 7;
        const float* we = (l == 0) ? we0 : (l == 1) ? we1 : we2;
        const float* ae = (l == 0) ? ae0 : (l == 1) ? ae1 : ae2;
        float s = 0.0f;
        for (int cc = 0; cc < NC; cc++) s += we[h * NC + cc] * ae[h * NC + cc];
        g_shead[t] = s;
    }
}

// ================= K2: bucket scatter =================
__global__ void k_scatter(const int* __restrict__ src, const int* __restrict__ dst,
                          const float* __restrict__ eattr, int E) {
    int e = blockIdx.x * blockDim.x + threadIdx.x;
    if (e < E) {
        int d = dst[e];
        float ea = eattr[e];
        int slot = atomicAdd(&g_deg[d], 1);
        if (slot < SLOTS) g_badj[d * SLOTS + slot] = make_int2(src[e], __float_as_int(ea));
        atomicAdd(&g_loop[d], ea);
    }
}

// ---- layers 1/2 transform: K=128 GEMM, FFMA2, 8 nodes/warp (halved W traffic) ----
__global__ void __launch_bounds__(256, 2) k_transform128(
        const float* __restrict__ w,
        const float* __restrict__ a_s,
        const float* __restrict__ a_d, int n) {
    __shared__ float xs[64 * NHC];           // 32KB x-tile
    int tile = blockIdx.x * 64;
    int t = threadIdx.x;
    for (int i = t; i < 64 * NHC / 4; i += 256) {
        int nl = i >> 5;
        int node = tile + nl;
        float4 v = make_float4(0.f, 0.f, 0.f, 0.f);
        if (node < n) v = *(const float4*)&g_feat[node * NHC + (i & 31) * 4];
        *(float4*)&xs[nl * NHC + (i & 31) * 4] = v;
    }
    __syncthreads();

    int c = t & 31;                          // cols 4c..4c+3
    int m = t >> 5;                          // warp id 0..7 -> nodes 8m..8m+7
    const float* xb = &xs[(m * 8) * NHC];
    u64 acc[8][2];
#pragma unroll
    for (int r = 0; r < 8; r++) { acc[r][0] = 0; acc[r][1] = 0; }
    const ulonglong2* wp = (const ulonglong2*)&w[c * 4];
    for (int k = 0; k < NHC; k += 4) {
        float4 xv[8];
#pragma unroll
        for (int r = 0; r < 8; r++) xv[r] = *(const float4*)&xb[r * NHC + k];
#pragma unroll
        for (int kk = 0; kk < 4; kk++) {
            ulonglong2 wv = wp[(k + kk) * (NHC / 4)];
#pragma unroll
            for (int r = 0; r < 8; r++) {
                u64 dr = dupf(((const float*)&xv[r])[kk]);
                acc[r][0] = ffma2(dr, wv.x, acc[r][0]);
                acc[r][1] = ffma2(dr, wv.y, acc[r][1]);
            }
        }
    }
    float4 asv = *(const float4*)&a_s[c * 4];
    float4 adv = *(const float4*)&a_d[c * 4];
    int node0 = tile + m * 8;
    int h = c >> 2;
#pragma unroll
    for (int r = 0; r < 8; r++) {
        float2 lo = unpack2(acc[r][0]);
        float2 hi = unpack2(acc[r][1]);
        float4 a4 = make_float4(lo.x, lo.y, hi.x, hi.y);
        float vs = a4.x*asv.x + a4.y*asv.y + a4.z*asv.z + a4.w*asv.w;
        float vd = a4.x*adv.x + a4.y*adv.y + a4.z*adv.z + a4.w*adv.w;
        vs += __shfl_down_sync(0xffffffffu, vs, 2, 4);
        vs += __shfl_down_sync(0xffffffffu, vs, 1, 4);
        vd += __shfl_down_sync(0xffffffffu, vd, 2, 4);
        vd += __shfl_down_sync(0xffffffffu, vd, 1, 4);
        int node = node0 + r;
        if (node < n) {
            if ((c & 3) == 0) {
                g_asrc[node * NH + h] = vs;
                g_adst[node * NH + h] = vd;
            }
            *(float4*)&g_hbuf[(u64)node * NHC + c * 4] = a4;
        }
    }
}

// ---- fused GAT dst pass: 8-edge int4 prefetch, shfl-free, warp per node ----
__global__ void __launch_bounds__(256) k_gat(const float* __restrict__ b,
                                             int layer, int withLoop, int n) {
    int warp = (blockIdx.x * blockDim.x + threadIdx.x) >> 5;
    int lane = threadIdx.x & 31;
    if (warp >= n) return;
    const int d = warp;
    const int hC = lane >> 2;

    float adst_h  = g_adst[d * NH + hC];
    float shead_h = g_shead[layer * NH + hC];

    int degFull = g_deg[d];
    float loopv = withLoop ? (g_loop[d] / fmaxf((float)degFull, 1.0f)) : 0.0f;

    int deg = min(degFull, SLOTS);
    int degTot = deg + withLoop;
    const int2* ba = &g_badj[d * SLOTS];

    float4 acc = make_float4(0.f, 0.f, 0.f, 0.f);
    float den = 0.0f;

    for (int base = 0; base < degTot; base += 8) {
        int4 q0 = *(const int4*)(ba + base + 0);
        int4 q1 = *(const int4*)(ba + base + 2);
        int4 q2 = *(const int4*)(ba + base + 4);
        int4 q3 = *(const int4*)(ba + base + 6);
        int   sv[8] = {q0.x, q0.z, q1.x, q1.z, q2.x, q2.z, q3.x, q3.z};
        int   ev[8] = {q0.y, q0.w, q1.y, q1.w, q2.y, q2.w, q3.y, q3.w};
#pragma unroll
        for (int j = 0; j < 8; j++) {
            int i = base + j;
            if (i >= degTot) break;
            int s; float ea;
            if (i < deg) { s = sv[j]; ea = __int_as_float(ev[j]); }
            else         { s = d;     ea = loopv; }
            float a = g_asrc[s * NH + hC] + adst_h + ea * shead_h;
            a = a > 0.0f ? a : 0.2f * a;
            float w = __expf(a);
            den += w;
            float4 hv = *(const float4*)&g_hbuf[s * NHC + lane * 4];
            acc.x += w * hv.x; acc.y += w * hv.y; acc.z += w * hv.z; acc.w += w * hv.w;
        }
    }

    float inv = 1.0f / (den + 1e-16f);
    float4 bv = *(const float4*)&b[lane * 4];
    float4 o;
    o.x = fmaxf(acc.x * inv + bv.x, 0.0f);
    o.y = fmaxf(acc.y * inv + bv.y, 0.0f);
    o.z = fmaxf(acc.z * inv + bv.z, 0.0f);
    o.w = fmaxf(acc.w * inv + bv.w, 0.0f);
    *(float4*)&g_feat[d * NHC + lane * 4] = o;
}

// ---- pooling (4-deep software pipeline) ----
__global__ void k_pool(const int* __restrict__ batch, int n) {
    const int CHUNK = 128;
    int n0 = blockIdx.x * CHUNK;
    int j = threadIdx.x;
    int lim = min(CHUNK, n - n0);
    float acc = 0.0f;
    int cur = -1, cl = 0;
    for (int i0 = 0; i0 < lim; i0 += 4) {
        float f[4]; int bi[4];
        int cnt = min(4, lim - i0);
#pragma unroll
        for (int k = 0; k < 4; k++) {
            if (k < cnt) {
                f[k]  = g_feat[(u64)(n0 + i0 + k) * NHC + j];
                bi[k] = batch[n0 + i0 + k];
            }
        }
#pragma unroll
        for (int k = 0; k < 4; k++) {
            if (k >= cnt) break;
            if (bi[k] != cur) {
                if (cur >= 0) {
                    atomicAdd(&g_gsum[cur * NHC + j], acc);
                    if (j == 0) atomicAdd(&g_gcnt[cur], (float)cl);
                }
                cur = bi[k]; acc = 0.0f; cl = 0;
            }
            acc += f[k];
            cl++;
        }
    }
    if (cur >= 0) {
        atomicAdd(&g_gsum[cur * NHC + j], acc);
        if (j == 0) atomicAdd(&g_gcnt[cur], (float)cl);
    }
}

// ---- final MLP head ----
__global__ void k_mlp(const float* __restrict__ fw1, const float* __restrict__ fb1,
                      const float* __restrict__ fw2, const float* __restrict__ fb2,
                      float* __restrict__ out) {
    int g = blockIdx.x, t = threadIdx.x;
    __shared__ float emb[NHC];
    __shared__ float ghs[64];
    float cnt = fmaxf(g_gcnt[g], 1.0f);
    emb[t]      = g_gsum[g * NHC + t] / cnt;
    emb[t + 64] = g_gsum[g * NHC + 64 + t] / cnt;
    __syncthreads();
    float acc = fb1[t];
#pragma unroll 8
    for (int k = 0; k < NHC; k++) acc += emb[k] * fw1[k * 64 + t];
    ghs[t] = fmaxf(acc, 0.0f);
    __syncthreads();
    if (t < 2) {
        float o = fb2[t];
        for (int k = 0; k < 64; k++) o += ghs[k] * fw2[k * 2 + t];
        out[g * 2 + t] = o;
    }
}

extern "C" void kernel_launch(void* const* d_in, const int* in_sizes, int n_in,
                              void* d_out, int out_size) {
    const float* x     = (const float*)d_in[0];
    const int*   ei    = (const int*)d_in[1];
    const float* eattr = (const float*)d_in[2];
    const int*   batch = (const int*)d_in[3];

    const float* W[3]  = {(const float*)d_in[4],  (const float*)d_in[10], (const float*)d_in[16]};
    const float* AS[3] = {(const float*)d_in[5],  (const float*)d_in[11], (const float*)d_in[17]};
    const float* AD[3] = {(const float*)d_in[6],  (const float*)d_in[12], (const float*)d_in[18]};
    const float* WE[3] = {(const float*)d_in[7],  (const float*)d_in[13], (const float*)d_in[19]};
    const float* AE[3] = {(const float*)d_in[8],  (const float*)d_in[14], (const float*)d_in[20]};
    const float* B[3]  = {(const float*)d_in[9],  (const float*)d_in[15], (const float*)d_in[21]};
    const float* fw1 = (const float*)d_in[22];
    const float* fb1 = (const float*)d_in[23];
    const float* fw2 = (const float*)d_in[24];
    const float* fb2 = (const float*)d_in[25];

    int N = in_sizes[3];
    int E = in_sizes[1] / 2;
    const int* src = ei;
    const int* dst = ei + E;

    int tb0 = (N * 32 + 255) / 256;
    int zb  = (N + 255) / 256;
    int pz  = (NG * NHC + 255) / 256;

    // 1: transform0 + zero + pool_zero + shead
    k_prep<<<tb0 + zb + pz + 1, 256>>>(x, W[0], AS[0], AD[0],
                                       WE[0], AE[0], WE[1], AE[1], WE[2], AE[2],
                                       N, tb0, zb, pz);
    // 2: bucket adjacency build (+ loop sums)
    k_scatter<<<(E + 255) / 256, 256>>>(src, dst, eattr, E);

    int gatBlocks  = (N * 32 + 255) / 256;
    int gemmBlocks = (N + 63) / 64;
    // 3: gat layer 0
    k_gat<<<gatBlocks, 256>>>(B[0], 0, 0, N);
    // 4: transform layer 1 (ncu capture slot)
    k_transform128<<<gemmBlocks, 256>>>(W[1], AS[1], AD[1], N);
    k_gat<<<gatBlocks, 256>>>(B[1], 1, 1, N);
    k_transform128<<<gemmBlocks, 256>>>(W[2], AS[2], AD[2], N);
    k_gat<<<gatBlocks, 256>>>(B[2], 2, 1, N);

    k_pool<<<(N + 127) / 128, NHC>>>(batch, N);
    k_mlp<<<NG, 64>>>(fw1, fb1, fw2, fb2, (float*)d_out);
}

// round 16
// speedup vs baseline: 1.0555x; 1.0194x over previous
#include <cuda_runtime.h>
#include <math.h>

#define NMAX 100000
#define EMAX 640000
#define NH 8
#define NC 16
#define NHC 128
#define NG 64
#define SLOTS 64

typedef unsigned long long u64;

// ---- scratch (static device globals; no allocation) ----
static __device__ float g_feat[NMAX * NHC];
static __device__ float g_hbuf[NMAX * NHC];
static __device__ float g_asrc[NMAX * NH];
static __device__ float g_adst[NMAX * NH];
static __device__ int   g_deg [NMAX];
static __device__ int2  g_badj[NMAX * SLOTS + 8];   // (src, ea bits) + pad for prefetch
static __device__ float g_shead[3 * NH];
static __device__ float g_gsum[NG * NHC];
static __device__ float g_gcnt[NG];

// ---- packed f32x2 helpers ----
__device__ __forceinline__ u64 ffma2(u64 a, u64 b, u64 c) {
    u64 r; asm("fma.rn.f32x2 %0, %1, %2, %3;" : "=l"(r) : "l"(a), "l"(b), "l"(c)); return r;
}
__device__ __forceinline__ u64 dupf(float x) {
    u64 r; asm("mov.b64 %0, {%1, %1};" : "=l"(r) : "f"(x)); return r;
}
__device__ __forceinline__ float2 unpack2(u64 v) {
    float2 r; asm("mov.b64 {%0, %1}, %2;" : "=f"(r.x), "=f"(r.y) : "l"(v)); return r;
}

// ================= K1: fused prep (transform0 | zero | pool_zero | shead) =================
__global__ void k_prep(const float* __restrict__ x,
                       const float* __restrict__ w,
                       const float* __restrict__ a_s,
                       const float* __restrict__ a_d,
                       const float* __restrict__ we0, const float* __restrict__ ae0,
                       const float* __restrict__ we1, const float* __restrict__ ae1,
                       const float* __restrict__ we2, const float* __restrict__ ae2,
                       int n, int tb0, int zb, int pz) {
    int bid = blockIdx.x;
    if (bid < tb0) {
        int gid = bid * 256 + threadIdx.x;
        int node = gid >> 5;
        if (node >= n) return;
        int c = gid & 31;
        float4 xv = *(const float4*)&x[node * 4];
        float4 w0 = *(const float4*)&w[0 * NHC + c * 4];
        float4 w1 = *(const float4*)&w[1 * NHC + c * 4];
        float4 w2 = *(const float4*)&w[2 * NHC + c * 4];
        float4 w3 = *(const float4*)&w[3 * NHC + c * 4];
        float4 acc;
        acc.x = xv.x * w0.x + xv.y * w1.x + xv.z * w2.x + xv.w * w3.x;
        acc.y = xv.x * w0.y + xv.y * w1.y + xv.z * w2.y + xv.w * w3.y;
        acc.z = xv.x * w0.z + xv.y * w1.z + xv.z * w2.z + xv.w * w3.z;
        acc.w = xv.x * w0.w + xv.y * w1.w + xv.z * w2.w + xv.w * w3.w;
        *(float4*)&g_hbuf[node * NHC + c * 4] = acc;
        float4 asv = *(const float4*)&a_s[c * 4];
        float4 adv = *(const float4*)&a_d[c * 4];
        float vs = acc.x * asv.x + acc.y * asv.y + acc.z * asv.z + acc.w * asv.w;
        float vd = acc.x * adv.x + acc.y * adv.y + acc.z * adv.z + acc.w * adv.w;
        vs += __shfl_down_sync(0xffffffffu, vs, 2, 4);
        vs += __shfl_down_sync(0xffffffffu, vs, 1, 4);
        vd += __shfl_down_sync(0xffffffffu, vd, 2, 4);
        vd += __shfl_down_sync(0xffffffffu, vd, 1, 4);
        if ((c & 3) == 0) {
            g_asrc[node * NH + (c >> 2)] = vs;
            g_adst[node * NH + (c >> 2)] = vd;
        }
    } else if (bid < tb0 + zb) {
        int i = (bid - tb0) * 256 + threadIdx.x;
        if (i < n) g_deg[i] = 0;
    } else if (bid < tb0 + zb + pz) {
        int i = (bid - tb0 - zb) * 256 + threadIdx.x;
        if (i < NG * NHC) g_gsum[i] = 0.0f;
        if (i < NG) g_gcnt[i] = 0.0f;
    } else {
        int t = threadIdx.x;
        if (t >= 24) return;
        int l = t >> 3, h = t & 7;
        const float* we = (l == 0) ? we0 : (l == 1) ? we1 : we2;
        const float* ae = (l == 0) ? ae0 : (l == 1) ? ae1 : ae2;
        float s = 0.0f;
        for (int cc = 0; cc < NC; cc++) s += we[h * NC + cc] * ae[h * NC + cc];
        g_shead[t] = s;
    }
}

// ================= K2: bucket scatter (single atomic per edge) =================
__global__ void k_scatter(const int* __restrict__ src, const int* __restrict__ dst,
                          const float* __restrict__ eattr, int E) {
    int e = blockIdx.x * blockDim.x + threadIdx.x;
    if (e < E) {
        int d = dst[e];
        int slot = atomicAdd(&g_deg[d], 1);
        if (slot < SLOTS) g_badj[d * SLOTS + slot] = make_int2(src[e], __float_as_int(eattr[e]));
    }
}

// ---- layers 1/2 transform: K=128 GEMM, FFMA2, 8 nodes/warp, unroll-2 W pipelining ----
__global__ void __launch_bounds__(256, 2) k_transform128(
        const float* __restrict__ w,
        const float* __restrict__ a_s,
        const float* __restrict__ a_d, int n) {
    __shared__ float xs[64 * NHC];           // 32KB x-tile
    int tile = blockIdx.x * 64;
    int t = threadIdx.x;
    for (int i = t; i < 64 * NHC / 4; i += 256) {
        int nl = i >> 5;
        int node = tile + nl;
        float4 v = make_float4(0.f, 0.f, 0.f, 0.f);
        if (node < n) v = *(const float4*)&g_feat[node * NHC + (i & 31) * 4];
        *(float4*)&xs[nl * NHC + (i & 31) * 4] = v;
    }
    __syncthreads();

    int c = t & 31;                          // cols 4c..4c+3
    int m = t >> 5;                          // warp id 0..7 -> nodes 8m..8m+7
    const float* xb = &xs[(m * 8) * NHC];
    u64 acc[8][2];
#pragma unroll
    for (int r = 0; r < 8; r++) { acc[r][0] = 0; acc[r][1] = 0; }
    const ulonglong2* wp = (const ulonglong2*)&w[c * 4];
#pragma unroll 2
    for (int k = 0; k < NHC; k += 4) {
        float4 xv[8];
#pragma unroll
        for (int r = 0; r < 8; r++) xv[r] = *(const float4*)&xb[r * NHC + k];
#pragma unroll
        for (int kk = 0; kk < 4; kk++) {
            ulonglong2 wv = wp[(k + kk) * (NHC / 4)];
#pragma unroll
            for (int r = 0; r < 8; r++) {
                u64 dr = dupf(((const float*)&xv[r])[kk]);
                acc[r][0] = ffma2(dr, wv.x, acc[r][0]);
                acc[r][1] = ffma2(dr, wv.y, acc[r][1]);
            }
        }
    }
    float4 asv = *(const float4*)&a_s[c * 4];
    float4 adv = *(const float4*)&a_d[c * 4];
    int node0 = tile + m * 8;
    int h = c >> 2;
#pragma unroll
    for (int r = 0; r < 8; r++) {
        float2 lo = unpack2(acc[r][0]);
        float2 hi = unpack2(acc[r][1]);
        float4 a4 = make_float4(lo.x, lo.y, hi.x, hi.y);
        float vs = a4.x*asv.x + a4.y*asv.y + a4.z*asv.z + a4.w*asv.w;
        float vd = a4.x*adv.x + a4.y*adv.y + a4.z*adv.z + a4.w*adv.w;
        vs += __shfl_down_sync(0xffffffffu, vs, 2, 4);
        vs += __shfl_down_sync(0xffffffffu, vs, 1, 4);
        vd += __shfl_down_sync(0xffffffffu, vd, 2, 4);
        vd += __shfl_down_sync(0xffffffffu, vd, 1, 4);
        int node = node0 + r;
        if (node < n) {
            if ((c & 3) == 0) {
                g_asrc[node * NH + h] = vs;
                g_adst[node * NH + h] = vd;
            }
            *(float4*)&g_hbuf[(u64)node * NHC + c * 4] = a4;
        }
    }
}

// ---- fused GAT dst pass: 8-edge int4 prefetch, shfl-free, warp per node ----
// self-loop handled as epilogue using easum accumulated from the bucket
__global__ void __launch_bounds__(256) k_gat(const float* __restrict__ b,
                                             int layer, int withLoop, int n) {
    int warp = (blockIdx.x * blockDim.x + threadIdx.x) >> 5;
    int lane = threadIdx.x & 31;
    if (warp >= n) return;
    const int d = warp;
    const int hC = lane >> 2;

    float adst_h  = g_adst[d * NH + hC];
    float shead_h = g_shead[layer * NH + hC];

    int degFull = g_deg[d];
    int deg = min(degFull, SLOTS);
    const int2* ba = &g_badj[d * SLOTS];

    float4 acc = make_float4(0.f, 0.f, 0.f, 0.f);
    float den = 0.0f;
    float easum = 0.0f;

    for (int base = 0; base < deg; base += 8) {
        int4 q0 = *(const int4*)(ba + base + 0);
        int4 q1 = *(const int4*)(ba + base + 2);
        int4 q2 = *(const int4*)(ba + base + 4);
        int4 q3 = *(const int4*)(ba + base + 6);
        int   sv[8] = {q0.x, q0.z, q1.x, q1.z, q2.x, q2.z, q3.x, q3.z};
        int   ev[8] = {q0.y, q0.w, q1.y, q1.w, q2.y, q2.w, q3.y, q3.w};
#pragma unroll
        for (int j = 0; j < 8; j++) {
            int i = base + j;
            if (i >= deg) break;
            int s = sv[j];
            float ea = __int_as_float(ev[j]);
            easum += ea;
            float a = g_asrc[s * NH + hC] + adst_h + ea * shead_h;
            a = fmaxf(a, 0.2f * a);
            float w = __expf(a);
            den += w;
            float4 hv = *(const float4*)&g_hbuf[s * NHC + lane * 4];
            acc.x += w * hv.x; acc.y += w * hv.y; acc.z += w * hv.z; acc.w += w * hv.w;
        }
    }

    if (withLoop) {
        float ea = easum / fmaxf((float)degFull, 1.0f);
        float a = g_asrc[d * NH + hC] + adst_h + ea * shead_h;
        a = fmaxf(a, 0.2f * a);
        float w = __expf(a);
        den += w;
        float4 hv = *(const float4*)&g_hbuf[d * NHC + lane * 4];
        acc.x += w * hv.x; acc.y += w * hv.y; acc.z += w * hv.z; acc.w += w * hv.w;
    }

    float inv = 1.0f / (den + 1e-16f);
    float4 bv = *(const float4*)&b[lane * 4];
    float4 o;
    o.x = fmaxf(acc.x * inv + bv.x, 0.0f);
    o.y = fmaxf(acc.y * inv + bv.y, 0.0f);
    o.z = fmaxf(acc.z * inv + bv.z, 0.0f);
    o.w = fmaxf(acc.w * inv + bv.w, 0.0f);
    *(float4*)&g_feat[d * NHC + lane * 4] = o;
}

// ---- pooling (4-deep software pipeline) ----
__global__ void k_pool(const int* __restrict__ batch, int n) {
    const int CHUNK = 128;
    int n0 = blockIdx.x * CHUNK;
    int j = threadIdx.x;
    int lim = min(CHUNK, n - n0);
    float acc = 0.0f;
    int cur = -1, cl = 0;
    for (int i0 = 0; i0 < lim; i0 += 4) {
        float f[4]; int bi[4];
        int cnt = min(4, lim - i0);
#pragma unroll
        for (int k = 0; k < 4; k++) {
            if (k < cnt) {
                f[k]  = g_feat[(u64)(n0 + i0 + k) * NHC + j];
                bi[k] = batch[n0 + i0 + k];
            }
        }
#pragma unroll
        for (int k = 0; k < 4; k++) {
            if (k >= cnt) break;
            if (bi[k] != cur) {
                if (cur >= 0) {
                    atomicAdd(&g_gsum[cur * NHC + j], acc);
                    if (j == 0) atomicAdd(&g_gcnt[cur], (float)cl);
                }
                cur = bi[k]; acc = 0.0f; cl = 0;
            }
            acc += f[k];
            cl++;
        }
    }
    if (cur >= 0) {
        atomicAdd(&g_gsum[cur * NHC + j], acc);
        if (j == 0) atomicAdd(&g_gcnt[cur], (float)cl);
    }
}

// ---- final MLP head ----
__global__ void k_mlp(const float* __restrict__ fw1, const float* __restrict__ fb1,
                      const float* __restrict__ fw2, const float* __restrict__ fb2,
                      float* __restrict__ out) {
    int g = blockIdx.x, t = threadIdx.x;
    __shared__ float emb[NHC];
    __shared__ float ghs[64];
    float cnt = fmaxf(g_gcnt[g], 1.0f);
    emb[t]      = g_gsum[g * NHC + t] / cnt;
    emb[t + 64] = g_gsum[g * NHC + 64 + t] / cnt;
    __syncthreads();
    float acc = fb1[t];
#pragma unroll 8
    for (int k = 0; k < NHC; k++) acc += emb[k] * fw1[k * 64 + t];
    ghs[t] = fmaxf(acc, 0.0f);
    __syncthreads();
    if (t < 2) {
        float o = fb2[t];
        for (int k = 0; k < 64; k++) o += ghs[k] * fw2[k * 2 + t];
        out[g * 2 + t] = o;
    }
}

extern "C" void kernel_launch(void* const* d_in, const int* in_sizes, int n_in,
                              void* d_out, int out_size) {
    const float* x     = (const float*)d_in[0];
    const int*   ei    = (const int*)d_in[1];
    const float* eattr = (const float*)d_in[2];
    const int*   batch = (const int*)d_in[3];

    const float* W[3]  = {(const float*)d_in[4],  (const float*)d_in[10], (const float*)d_in[16]};
    const float* AS[3] = {(const float*)d_in[5],  (const float*)d_in[11], (const float*)d_in[17]};
    const float* AD[3] = {(const float*)d_in[6],  (const float*)d_in[12], (const float*)d_in[18]};
    const float* WE[3] = {(const float*)d_in[7],  (const float*)d_in[13], (const float*)d_in[19]};
    const float* AE[3] = {(const float*)d_in[8],  (const float*)d_in[14], (const float*)d_in[20]};
    const float* B[3]  = {(const float*)d_in[9],  (const float*)d_in[15], (const float*)d_in[21]};
    const float* fw1 = (const float*)d_in[22];
    const float* fb1 = (const float*)d_in[23];
    const float* fw2 = (const float*)d_in[24];
    const float* fb2 = (const float*)d_in[25];

    int N = in_sizes[3];
    int E = in_sizes[1] / 2;
    const int* src = ei;
    const int* dst = ei + E;

    int tb0 = (N * 32 + 255) / 256;
    int zb  = (N + 255) / 256;
    int pz  = (NG * NHC + 255) / 256;

    // 1: transform0 + zero + pool_zero + shead
    k_prep<<<tb0 + zb + pz + 1, 256>>>(x, W[0], AS[0], AD[0],
                                       WE[0], AE[0], WE[1], AE[1], WE[2], AE[2],
                                       N, tb0, zb, pz);
    // 2: bucket adjacency build
    k_scatter<<<(E + 255) / 256, 256>>>(src, dst, eattr, E);

    int gatBlocks  = (N * 32 + 255) / 256;
    int gemmBlocks = (N + 63) / 64;
    // 3: gat layer 0
    k_gat<<<gatBlocks, 256>>>(B[0], 0, 0, N);
    // 4: transform layer 1 (ncu capture slot)
    k_transform128<<<gemmBlocks, 256>>>(W[1], AS[1], AD[1], N);
    k_gat<<<gatBlocks, 256>>>(B[1], 1, 1, N);
    k_transform128<<<gemmBlocks, 256>>>(W[2], AS[2], AD[2], N);
    k_gat<<<gatBlocks, 256>>>(B[2], 2, 1, N);

    k_pool<<<(N + 127) / 128, NHC>>>(batch, N);
    k_mlp<<<NG, 64>>>(fw1, fb1, fw2, fb2, (float*)d_out);
}